// round 16
// baseline (speedup 1.0000x reference)
#include <cuda_runtime.h>
#include <cuda_fp16.h>
#include <cstdint>
#include <math.h>

#define BB 4
#define SS 2048
#define DD 1024
#define HH 16
#define DKK 64
#define M_TOT (BB*SS)
#define MA (M_TOT*DD)
#define MW (DD*DD)
#define NPERS 304   // persistent CTAs (2 x 152 SMs)

// ---------------- scratch (device globals; allocation-free) ----------------
__device__ __half g_Xh[3 * MA];   // activations (single fp16)
__device__ __half g_W4[4 * MW];   // weights (single fp16)
__device__ __half g_Qh[MA];       // Q single fp16
__device__ __half g_Kh[MA];       // K single fp16
__device__ __half g_Vh[MA];       // V single fp16
__device__ __half g_Ctx[MA];      // ctx single fp16 (attn -> O gemm)

// ---------------- helpers ----------------
__device__ __forceinline__ uint32_t smem_u32(const void* p) {
    uint32_t a;
    asm("{ .reg .u64 t; cvta.to.shared.u64 t, %1; cvt.u32.u64 %0, t; }" : "=r"(a) : "l"(p));
    return a;
}
__device__ __forceinline__ void ldsm_x4(uint32_t* r, uint32_t addr) {
    asm volatile("ldmatrix.sync.aligned.m8n8.x4.shared.b16 {%0,%1,%2,%3}, [%4];"
                 : "=r"(r[0]), "=r"(r[1]), "=r"(r[2]), "=r"(r[3]) : "r"(addr));
}
__device__ __forceinline__ void ldsm_x4t(uint32_t* r, uint32_t addr) {
    asm volatile("ldmatrix.sync.aligned.m8n8.x4.trans.shared.b16 {%0,%1,%2,%3}, [%4];"
                 : "=r"(r[0]), "=r"(r[1]), "=r"(r[2]), "=r"(r[3]) : "r"(addr));
}
__device__ __forceinline__ void mma_f16(float* d, const uint32_t* a, const uint32_t* b) {
    asm volatile("mma.sync.aligned.m16n8k16.row.col.f32.f16.f16.f32 "
                 "{%0,%1,%2,%3}, {%4,%5,%6,%7}, {%8,%9}, {%0,%1,%2,%3};"
                 : "+f"(d[0]), "+f"(d[1]), "+f"(d[2]), "+f"(d[3])
                 : "r"(a[0]), "r"(a[1]), "r"(a[2]), "r"(a[3]), "r"(b[0]), "r"(b[1]));
}
__device__ __forceinline__ void cpa16(uint32_t dst, const void* src) {
    asm volatile("cp.async.cg.shared.global [%0], [%1], 16;" :: "r"(dst), "l"(src));
}
__device__ __forceinline__ void cpa_commit() { asm volatile("cp.async.commit_group;"); }
template<int N> __device__ __forceinline__ void cpa_wait() {
    asm volatile("cp.async.wait_group %0;" :: "n"(N));
}
__device__ __forceinline__ uint32_t pack2h(float x, float y) {
    __half2 h = __floats2half2_rn(x, y);
    return *(uint32_t*)&h;
}

// ---------------- one-shot fp32->fp16 convert of all 7 input tensors ----------------
struct SplitArgs { const float* src[7]; };
#define NA4 (MA/4)
#define NW4 (MW/4)
#define TOT4 (3*NA4 + 4*NW4)

__global__ void split7(SplitArgs a) {
    const int i = blockIdx.x * blockDim.x + threadIdx.x;
#pragma unroll
    for (int rep = 0; rep < 2; rep++) {
        const int j = i + rep * (TOT4 / 2);
        int seg, off;
        if (j < 3 * NA4) { seg = j / NA4; off = j - seg * NA4; }
        else { const int t = j - 3 * NA4; seg = 3 + t / NW4; off = t - (seg - 3) * NW4; }
        __half* dst = (seg < 3) ? (g_Xh + (size_t)seg * MA)
                                : (g_W4 + (size_t)(seg - 3) * MW);
        float4 v = ((const float4*)a.src[seg])[off];
        ((uint32_t*)dst)[2 * off]     = pack2h(v.x, v.y);
        ((uint32_t*)dst)[2 * off + 1] = pack2h(v.z, v.w);
    }
}

// ---------------- HMMA fp16 GEMM core: 128x128 tile, 3-stage, 2 CTAs/SM ----------------
#define G_B     10240u
#define G_STAGE 18944u
#define G_DSMEM (3 * 18944)

__device__ __forceinline__ void gemm_core(
    const __half* __restrict__ Ah, const __half* __restrict__ Wh,
    const float* __restrict__ bias, float* __restrict__ Cout, int which,
    int bn, int bm, char* dynsm)
{
    const uint32_t sb = smem_u32(dynsm);
    const int tid = threadIdx.x, lane = tid & 31, wid = tid >> 5;
    const int wm = (wid >> 1) * 32;
    const int wn = (wid & 1) * 64;

    __syncthreads();   // previous tile's smem reads must drain before re-staging

    float acc[2][8][4];
#pragma unroll
    for (int mi = 0; mi < 2; mi++)
#pragma unroll
        for (int ni = 0; ni < 8; ni++)
#pragma unroll
            for (int r = 0; r < 4; r++) acc[mi][ni][r] = 0.f;

    auto issue = [&](int kc, int stg) {
        const uint32_t base = sb + stg * G_STAGE;
#pragma unroll
        for (int it = 0; it < 2; it++) {
            const int c = it * 256 + tid;
            const int ar = c >> 2, aq = c & 3;
            cpa16(base + (uint32_t)(ar * 80 + aq * 16),
                  Ah + (size_t)(bm + ar) * DD + kc * 32 + aq * 8);
            const int br = c >> 4, bq = c & 15;
            cpa16(base + G_B + (uint32_t)(br * 272 + bq * 16),
                  Wh + (size_t)(kc * 32 + br) * DD + bn + bq * 8);
        }
    };

    issue(0, 0); cpa_commit();
    issue(1, 1); cpa_commit();
    int scur = 0;

    for (int kc = 0; kc < 32; kc++) {
        cpa_wait<1>();
        __syncthreads();
        if (kc < 30) { int sn = scur + 2; if (sn >= 3) sn -= 3; issue(kc + 2, sn); }
        cpa_commit();

        const uint32_t st = sb + scur * G_STAGE;
#pragma unroll
        for (int ks = 0; ks < 2; ks++) {
            uint32_t ah[2][4];
#pragma unroll
            for (int mi = 0; mi < 2; mi++) {
                const uint32_t aoff = (uint32_t)((wm + mi * 16 + (lane & 15)) * 80
                                                 + (ks * 16 + (lane >> 4) * 8) * 2);
                ldsm_x4(ah[mi], st + aoff);
            }
#pragma unroll
            for (int p = 0; p < 4; p++) {
                uint32_t bh4[4];
                const uint32_t boff = (uint32_t)(
                    (ks * 16 + ((lane >> 3) & 1) * 8 + (lane & 7)) * 272
                    + (wn + p * 16 + ((lane >> 4) & 1) * 8) * 2);
                ldsm_x4t(bh4, st + G_B + boff);
#pragma unroll
                for (int half = 0; half < 2; half++)
#pragma unroll
                    for (int mi = 0; mi < 2; mi++)
                        mma_f16(acc[mi][p * 2 + half], ah[mi], &bh4[half * 2]);
            }
        }
        scur = (scur + 1 == 3) ? 0 : scur + 1;
    }

    const int g = lane >> 2, t2 = (lane & 3) * 2;
#pragma unroll
    for (int mi = 0; mi < 2; mi++) {
#pragma unroll
        for (int ni = 0; ni < 8; ni++) {
#pragma unroll
            for (int half = 0; half < 2; half++) {
                const int row = bm + wm + mi * 16 + g + half * 8;
                const int col = bn + wn + ni * 8 + t2;
                const float vx = acc[mi][ni][half * 2 + 0] + bias[col];
                const float vy = acc[mi][ni][half * 2 + 1] + bias[col + 1];
                if (which < 3) {
                    const int b = row >> 11, s = row & (SS - 1);
                    const int hh = col >> 6, d = col & (DKK - 1);
                    const size_t off = ((size_t)(b * HH + hh) * SS + s) * DKK + d;
                    __half* dst = (which == 0) ? g_Qh : (which == 1) ? g_Kh : g_Vh;
                    *(uint32_t*)&dst[off] = pack2h(vx, vy);
                } else {
                    float2 v; v.x = vx; v.y = vy;
                    *(float2*)&Cout[(size_t)row * DD + col] = v;
                }
            }
        }
    }
}

// persistent: 1536 tiles = 3 (z) x 64 (bm) x 8 (bn)
__global__ __launch_bounds__(256, 2) void gemm_qkv(
    const float* __restrict__ bq, const float* __restrict__ bk,
    const float* __restrict__ bv)
{
    extern __shared__ char dynsm[];
    for (int t = blockIdx.x; t < 1536; t += gridDim.x) {
        const int z = t >> 9;           // /512
        const int r = t & 511;
        const int bn = (r & 7) * 128;
        const int bm = (r >> 3) * 128;
        const float* bias = (z == 0) ? bq : (z == 1) ? bk : bv;
        gemm_core(g_Xh + (size_t)z * MA, g_W4 + (size_t)z * MW,
                  bias, nullptr, z, bn, bm, dynsm);
    }
}

// persistent: 512 tiles = 64 (bm) x 8 (bn)
__global__ __launch_bounds__(256, 2) void gemm_o(
    const float* __restrict__ bo, float* __restrict__ out)
{
    extern __shared__ char dynsm[];
    for (int t = blockIdx.x; t < 512; t += gridDim.x) {
        const int bn = (t & 7) * 128;
        const int bm = (t >> 3) * 128;
        gemm_core(g_Ctx, g_W4 + (size_t)3 * MW, bo, out, 3, bn, bm, dynsm);
    }
}

// ---------------- flash attention: 64-query tile, persistent, no-rescale softmax ----
#define A_VH  9216u
#define A_STAGE 18432u
#define A_MASK  (4 * 18432)
#define A_DSMEM (4 * 18432 + 4 * 64 * 4)
#define NTILE (SS / 64)   // 32
#define NT_A  (32 * HH * BB)   // 2048 attention tiles

__global__ __launch_bounds__(256, 2) void attn_mma(const float* __restrict__ mask)
{
    extern __shared__ char dynsm[];
    const uint32_t sb = smem_u32(dynsm);
    __half* smh = (__half*)dynsm;
    float* sMask = (float*)(dynsm + A_MASK);

    const int tid = threadIdx.x, lane = tid & 31;
    const int qw = tid >> 6;          // q-group 0..3 (16 rows each)
    const int kw = (tid >> 5) & 1;    // key-group 0..1
    const int g = lane >> 2, t2 = (lane & 3) * 2;

    for (int tile = blockIdx.x; tile < NT_A; tile += gridDim.x) {
        const int qt = tile & 31;
        const int hd = (tile >> 5) & (HH - 1);
        const int b  = tile >> 9;

        const size_t bhoff = (size_t)(b * HH + hd) * SS;
        const __half* Qhg = g_Qh + (bhoff + qt * 64) * DKK;
        const __half* Khg = g_Kh + bhoff * DKK;
        const __half* Vhg = g_Vh + bhoff * DKK;
        const float* mrow = mask + (size_t)b * SS;

        __syncthreads();   // previous tile's merge-smem reads must drain

        // ---- stage Q (64x64 fp16) through smem, extract per-warp 16-row frags ----
        for (int i = tid; i < 64 * 8; i += 256) {
            const int r = i >> 3, c = (i & 7) * 8;
            *(uint4*)&smh[r * 72 + c] = *(const uint4*)(Qhg + r * DKK + c);
        }
        __syncthreads();
        uint32_t qh[4][4];
#pragma unroll
        for (int ks = 0; ks < 4; ks++) {
            const uint32_t off = (uint32_t)((qw * 16 + (lane & 15)) * 144
                                            + (ks * 16 + (lane >> 4) * 8) * 2);
            ldsm_x4(qh[ks], sb + off);
        }
        __syncthreads();

        auto issue = [&](int kt, int stg) {
            const uint32_t base = sb + stg * A_STAGE;
            const size_t goff = (size_t)kt * 64 * DKK;
#pragma unroll
            for (int it = 0; it < 2; it++) {
                const int c = it * 256 + tid;
                const int r = c >> 3, cc = c & 7;
                const uint32_t d = base + (uint32_t)(r * 144 + cc * 16);
                const size_t s = goff + (size_t)r * DKK + cc * 8;
                cpa16(d,        Khg + s);
                cpa16(d + A_VH, Vhg + s);
            }
        };

        float o[8][4];
#pragma unroll
        for (int nd = 0; nd < 8; nd++)
#pragma unroll
            for (int r = 0; r < 4; r++) o[nd][r] = 0.f;
        float lr0 = 0.f, lr1 = 0.f;
        float s[4][4];
        uint32_t pf[2][4];

        auto qkstep = [&](uint32_t st) {
#pragma unroll
            for (int ng = 0; ng < 4; ng++)
#pragma unroll
                for (int r = 0; r < 4; r++) s[ng][r] = 0.f;
#pragma unroll
            for (int ks = 0; ks < 4; ks++) {
                uint32_t bh4[2][4];
#pragma unroll
                for (int pg = 0; pg < 2; pg++) {
                    const uint32_t a = st + (uint32_t)(
                        (kw * 32 + pg * 16 + ((lane >> 4) & 1) * 8 + (lane & 7)) * 144
                        + (ks * 16 + ((lane >> 3) & 1) * 8) * 2);
                    ldsm_x4(bh4[pg], a);
                }
#pragma unroll
                for (int pg = 0; pg < 2; pg++)
#pragma unroll
                    for (int half = 0; half < 2; half++)
                        mma_f16(s[pg * 2 + half], qh[ks], &bh4[pg][half * 2]);
            }
        };

        auto pvstep = [&](uint32_t st) {
#pragma unroll
            for (int ksp = 0; ksp < 2; ksp++) {
#pragma unroll
                for (int pd = 0; pd < 4; pd++) {
                    uint32_t bh4[4];
                    const uint32_t a = st + A_VH + (uint32_t)(
                        (kw * 32 + ksp * 16 + ((lane >> 3) & 1) * 8 + (lane & 7)) * 144
                        + (pd * 16 + ((lane >> 4) & 1) * 8) * 2);
                    ldsm_x4t(bh4, a);
#pragma unroll
                    for (int half = 0; half < 2; half++)
                        mma_f16(o[pd * 2 + half], pf[ksp], &bh4[half * 2]);
                }
            }
        };

        auto smstep = [&](const float* mk) {
#pragma unroll
            for (int ng = 0; ng < 4; ng++) {
                const float mk0 = mk[ng * 8 + t2], mk1 = mk[ng * 8 + t2 + 1];
                s[ng][0] = __expf(s[ng][0] * 0.125f + mk0);
                s[ng][1] = __expf(s[ng][1] * 0.125f + mk1);
                s[ng][2] = __expf(s[ng][2] * 0.125f + mk0);
                s[ng][3] = __expf(s[ng][3] * 0.125f + mk1);
                lr0 += s[ng][0] + s[ng][1];
                lr1 += s[ng][2] + s[ng][3];
            }
#pragma unroll
            for (int ksp = 0; ksp < 2; ksp++) {
                pf[ksp][0] = pack2h(s[2 * ksp][0],     s[2 * ksp][1]);
                pf[ksp][1] = pack2h(s[2 * ksp][2],     s[2 * ksp][3]);
                pf[ksp][2] = pack2h(s[2 * ksp + 1][0], s[2 * ksp + 1][1]);
                pf[ksp][3] = pack2h(s[2 * ksp + 1][2], s[2 * ksp + 1][3]);
            }
        };

        issue(0, 0); cpa_commit();
        issue(1, 1); cpa_commit();
        issue(2, 2); cpa_commit();
        if (tid < 64) {
            sMask[tid]       = mrow[tid] * (-1e9f);
            sMask[64 + tid]  = mrow[64 + tid] * (-1e9f);
            sMask[128 + tid] = mrow[128 + tid] * (-1e9f);
        }
        cpa_wait<2>();
        __syncthreads();
        qkstep(sb + 0 * A_STAGE);
        smstep(sMask + 0 * 64 + kw * 32);

        for (int t = 0; t < NTILE - 1; t++) {
            if (t + 3 < NTILE) cpa_wait<1>(); else cpa_wait<0>();
            __syncthreads();
            if (t + 3 < NTILE) {
                const int sn = (t + 3) & 3;
                issue(t + 3, sn);
                if (tid < 64) sMask[sn * 64 + tid] = mrow[(t + 3) * 64 + tid] * (-1e9f);
                cpa_commit();
            }
            qkstep(sb + ((t + 1) & 3) * A_STAGE);
            pvstep(sb + (t & 3) * A_STAGE);
            smstep(sMask + ((t + 1) & 3) * 64 + kw * 32);
        }
        pvstep(sb + ((NTILE - 1) & 3) * A_STAGE);

        lr0 += __shfl_xor_sync(0xffffffffu, lr0, 1);
        lr0 += __shfl_xor_sync(0xffffffffu, lr0, 2);
        lr1 += __shfl_xor_sync(0xffffffffu, lr1, 1);
        lr1 += __shfl_xor_sync(0xffffffffu, lr1, 2);

        __syncthreads();

        // ---- merge key-halves (plain sums), write ctx single fp16 ----
        float* sO = (float*)dynsm;                      // [64][66]
        float* sL = (float*)(dynsm + 64 * 66 * 4);      // [64]
        if (kw == 1) {
#pragma unroll
            for (int hf = 0; hf < 2; hf++) {
                const int idx = qw * 16 + g + hf * 8;
#pragma unroll
                for (int nd = 0; nd < 8; nd++) {
                    sO[idx * 66 + nd * 8 + t2]     = o[nd][hf * 2 + 0];
                    sO[idx * 66 + nd * 8 + t2 + 1] = o[nd][hf * 2 + 1];
                }
                if ((lane & 3) == 0) sL[idx] = hf ? lr1 : lr0;
            }
        }
        __syncthreads();
        if (kw == 0) {
#pragma unroll
            for (int hf = 0; hf < 2; hf++) {
                const int idx = qw * 16 + g + hf * 8;
                const float lh = hf ? lr1 : lr0;
                const float inv = 1.f / (lh + sL[idx]);
#pragma unroll
                for (int nd = 0; nd < 8; nd++) {
                    const float p0 = (o[nd][hf * 2 + 0] + sO[idx * 66 + nd * 8 + t2]) * inv;
                    const float p1 = (o[nd][hf * 2 + 1] + sO[idx * 66 + nd * 8 + t2 + 1]) * inv;
                    const size_t off = ((size_t)b * SS + qt * 64 + idx) * DD
                                       + hd * DKK + nd * 8 + t2;
                    *(uint32_t*)&g_Ctx[off] = pack2h(p0, p1);
                }
            }
        }
    }
}

// ---------------------------------------------------------------------------
extern "C" void kernel_launch(void* const* d_in, const int* in_sizes, int n_in,
                              void* d_out, int out_size)
{
    (void)in_sizes; (void)n_in; (void)out_size;
    const float* query = (const float*)d_in[0];
    const float* key   = (const float*)d_in[1];
    const float* value = (const float*)d_in[2];
    const float* mask  = (const float*)d_in[3];
    const float* Wq = (const float*)d_in[4];
    const float* bq = (const float*)d_in[5];
    const float* Wk = (const float*)d_in[6];
    const float* bk = (const float*)d_in[7];
    const float* Wv = (const float*)d_in[8];
    const float* bv = (const float*)d_in[9];
    const float* Wo = (const float*)d_in[10];
    const float* bo = (const float*)d_in[11];
    float* out = (float*)d_out;

    cudaFuncSetAttribute(gemm_qkv, cudaFuncAttributeMaxDynamicSharedMemorySize, G_DSMEM);
    cudaFuncSetAttribute(gemm_o,   cudaFuncAttributeMaxDynamicSharedMemorySize, G_DSMEM);
    cudaFuncSetAttribute(attn_mma, cudaFuncAttributeMaxDynamicSharedMemorySize, A_DSMEM);

    SplitArgs sa;
    sa.src[0] = query; sa.src[1] = key; sa.src[2] = value;
    sa.src[3] = Wq; sa.src[4] = Wk; sa.src[5] = Wv; sa.src[6] = Wo;

    split7<<<TOT4 / 512, 256>>>(sa);
    gemm_qkv<<<NPERS, 256, G_DSMEM>>>(bq, bk, bv);
    attn_mma<<<NPERS, 256, A_DSMEM>>>(mask);
    gemm_o<<<NPERS, 256, G_DSMEM>>>(bo, out);
}

// round 17
// speedup vs baseline: 1.0399x; 1.0399x over previous
#include <cuda_runtime.h>
#include <cuda_fp16.h>
#include <cstdint>
#include <math.h>

#define BB 4
#define SS 2048
#define DD 1024
#define HH 16
#define DKK 64
#define M_TOT (BB*SS)
#define MA (M_TOT*DD)
#define MW (DD*DD)

// ---------------- scratch (device globals; allocation-free) ----------------
__device__ __half g_Xh[3 * MA];   // activations (single fp16)
__device__ __half g_W4[4 * MW];   // weights (single fp16)
__device__ __half g_Qh[MA];       // Q single fp16
__device__ __half g_Kh[MA];       // K single fp16
__device__ __half g_Vh[MA];       // V single fp16
__device__ __half g_Ctx[MA];      // ctx single fp16 (attn -> O gemm)

// ---------------- helpers ----------------
__device__ __forceinline__ uint32_t smem_u32(const void* p) {
    uint32_t a;
    asm("{ .reg .u64 t; cvta.to.shared.u64 t, %1; cvt.u32.u64 %0, t; }" : "=r"(a) : "l"(p));
    return a;
}
__device__ __forceinline__ void ldsm_x4(uint32_t* r, uint32_t addr) {
    asm volatile("ldmatrix.sync.aligned.m8n8.x4.shared.b16 {%0,%1,%2,%3}, [%4];"
                 : "=r"(r[0]), "=r"(r[1]), "=r"(r[2]), "=r"(r[3]) : "r"(addr));
}
__device__ __forceinline__ void ldsm_x4t(uint32_t* r, uint32_t addr) {
    asm volatile("ldmatrix.sync.aligned.m8n8.x4.trans.shared.b16 {%0,%1,%2,%3}, [%4];"
                 : "=r"(r[0]), "=r"(r[1]), "=r"(r[2]), "=r"(r[3]) : "r"(addr));
}
__device__ __forceinline__ void mma_f16(float* d, const uint32_t* a, const uint32_t* b) {
    asm volatile("mma.sync.aligned.m16n8k16.row.col.f32.f16.f16.f32 "
                 "{%0,%1,%2,%3}, {%4,%5,%6,%7}, {%8,%9}, {%0,%1,%2,%3};"
                 : "+f"(d[0]), "+f"(d[1]), "+f"(d[2]), "+f"(d[3])
                 : "r"(a[0]), "r"(a[1]), "r"(a[2]), "r"(a[3]), "r"(b[0]), "r"(b[1]));
}
__device__ __forceinline__ void cpa16(uint32_t dst, const void* src) {
    asm volatile("cp.async.cg.shared.global [%0], [%1], 16;" :: "r"(dst), "l"(src));
}
__device__ __forceinline__ void cpa_commit() { asm volatile("cp.async.commit_group;"); }
template<int N> __device__ __forceinline__ void cpa_wait() {
    asm volatile("cp.async.wait_group %0;" :: "n"(N));
}
__device__ __forceinline__ uint32_t pack2h(float x, float y) {
    __half2 h = __floats2half2_rn(x, y);
    return *(uint32_t*)&h;
}

// ---------------- one-shot fp32->fp16 convert of all 7 input tensors ----------------
struct SplitArgs { const float* src[7]; };
#define NA4 (MA/4)
#define NW4 (MW/4)
#define TOT4 (3*NA4 + 4*NW4)

__global__ void split7(SplitArgs a) {
    const int i = blockIdx.x * blockDim.x + threadIdx.x;
#pragma unroll
    for (int rep = 0; rep < 2; rep++) {
        const int j = i + rep * (TOT4 / 2);
        int seg, off;
        if (j < 3 * NA4) { seg = j / NA4; off = j - seg * NA4; }
        else { const int t = j - 3 * NA4; seg = 3 + t / NW4; off = t - (seg - 3) * NW4; }
        __half* dst = (seg < 3) ? (g_Xh + (size_t)seg * MA)
                                : (g_W4 + (size_t)(seg - 3) * MW);
        float4 v = ((const float4*)a.src[seg])[off];
        ((uint32_t*)dst)[2 * off]     = pack2h(v.x, v.y);
        ((uint32_t*)dst)[2 * off + 1] = pack2h(v.z, v.w);
    }
}

// ---------------- HMMA fp16 GEMM: 128x128 tile, BK=64, 3-stage, 2 CTAs/SM ----------
// stage: A 128x72h (18432B) + B 64x136h (17408B) = 35840B; 3 stages = 105KB/CTA
#define G_B     18432u
#define G_STAGE 35840u
#define G_DSMEM (3 * 35840)

__device__ __forceinline__ void gemm_core(
    const __half* __restrict__ Ah, const __half* __restrict__ Wh,
    const float* __restrict__ bias, float* __restrict__ Cout, int which, char* dynsm)
{
    const uint32_t sb = smem_u32(dynsm);
    const int tid = threadIdx.x, lane = tid & 31, wid = tid >> 5;
    const int wm = (wid >> 1) * 32;
    const int wn = (wid & 1) * 64;
    const int bn = blockIdx.x * 128, bm = blockIdx.y * 128;

    float acc[2][8][4];
#pragma unroll
    for (int mi = 0; mi < 2; mi++)
#pragma unroll
        for (int ni = 0; ni < 8; ni++)
#pragma unroll
            for (int r = 0; r < 4; r++) acc[mi][ni][r] = 0.f;

    // BK=64 stage loader: A 128x64h (4 granules/thread), B 64x128h (4/thread)
    auto issue = [&](int kc, int stg) {
        const uint32_t base = sb + stg * G_STAGE;
#pragma unroll
        for (int it = 0; it < 4; it++) {
            const int c = it * 256 + tid;
            const int ar = c >> 3, aq = c & 7;
            cpa16(base + (uint32_t)(ar * 144 + aq * 16),
                  Ah + (size_t)(bm + ar) * DD + kc * 64 + aq * 8);
            const int br = c >> 4, bq = c & 15;
            cpa16(base + G_B + (uint32_t)(br * 272 + bq * 16),
                  Wh + (size_t)(kc * 64 + br) * DD + bn + bq * 8);
        }
    };

    issue(0, 0); cpa_commit();
    issue(1, 1); cpa_commit();
    int scur = 0;

    for (int kc = 0; kc < 16; kc++) {
        cpa_wait<1>();
        __syncthreads();
        if (kc < 14) { int sn = scur + 2; if (sn >= 3) sn -= 3; issue(kc + 2, sn); }
        cpa_commit();

        const uint32_t st = sb + scur * G_STAGE;
#pragma unroll
        for (int ks = 0; ks < 4; ks++) {
            uint32_t ah[2][4];
#pragma unroll
            for (int mi = 0; mi < 2; mi++) {
                const uint32_t aoff = (uint32_t)((wm + mi * 16 + (lane & 15)) * 144
                                                 + (ks * 16 + (lane >> 4) * 8) * 2);
                ldsm_x4(ah[mi], st + aoff);
            }
#pragma unroll
            for (int p = 0; p < 4; p++) {
                uint32_t bh4[4];
                const uint32_t boff = (uint32_t)(
                    (ks * 16 + ((lane >> 3) & 1) * 8 + (lane & 7)) * 272
                    + (wn + p * 16 + ((lane >> 4) & 1) * 8) * 2);
                ldsm_x4t(bh4, st + G_B + boff);
#pragma unroll
                for (int half = 0; half < 2; half++)
#pragma unroll
                    for (int mi = 0; mi < 2; mi++)
                        mma_f16(acc[mi][p * 2 + half], ah[mi], &bh4[half * 2]);
            }
        }
        scur = (scur + 1 == 3) ? 0 : scur + 1;
    }

    const int g = lane >> 2, t2 = (lane & 3) * 2;
#pragma unroll
    for (int mi = 0; mi < 2; mi++) {
#pragma unroll
        for (int ni = 0; ni < 8; ni++) {
#pragma unroll
            for (int half = 0; half < 2; half++) {
                const int row = bm + wm + mi * 16 + g + half * 8;
                const int col = bn + wn + ni * 8 + t2;
                const float vx = acc[mi][ni][half * 2 + 0] + bias[col];
                const float vy = acc[mi][ni][half * 2 + 1] + bias[col + 1];
                if (which < 3) {
                    const int b = row >> 11, s = row & (SS - 1);
                    const int hh = col >> 6, d = col & (DKK - 1);
                    const size_t off = ((size_t)(b * HH + hh) * SS + s) * DKK + d;
                    __half* dst = (which == 0) ? g_Qh : (which == 1) ? g_Kh : g_Vh;
                    *(uint32_t*)&dst[off] = pack2h(vx, vy);
                } else {
                    float2 v; v.x = vx; v.y = vy;
                    *(float2*)&Cout[(size_t)row * DD + col] = v;
                }
            }
        }
    }
}

__global__ __launch_bounds__(256, 2) void gemm_qkv(
    const float* __restrict__ bq, const float* __restrict__ bk,
    const float* __restrict__ bv)
{
    extern __shared__ char dynsm[];
    const int z = blockIdx.z;
    const float* bias = (z == 0) ? bq : (z == 1) ? bk : bv;
    gemm_core(g_Xh + (size_t)z * MA, g_W4 + (size_t)z * MW, bias, nullptr, z, dynsm);
}

__global__ __launch_bounds__(256, 2) void gemm_o(
    const float* __restrict__ bo, float* __restrict__ out)
{
    extern __shared__ char dynsm[];
    gemm_core(g_Ctx, g_W4 + (size_t)3 * MW, bo, out, 3, dynsm);
}

// ---------------- flash attention: 64-query CTA, 2 CTAs/SM, no-rescale softmax -----
// (Round-15 version, unchanged)
#define A_VH  9216u
#define A_STAGE 18432u
#define A_MASK  (4 * 18432)
#define A_DSMEM (4 * 18432 + 4 * 64 * 4)
#define NTILE (SS / 64)   // 32

__global__ __launch_bounds__(256, 2) void attn_mma(const float* __restrict__ mask)
{
    extern __shared__ char dynsm[];
    const uint32_t sb = smem_u32(dynsm);
    __half* smh = (__half*)dynsm;
    float* sMask = (float*)(dynsm + A_MASK);

    const int qt = blockIdx.x, hd = blockIdx.y, b = blockIdx.z;
    const int tid = threadIdx.x, lane = tid & 31;
    const int qw = tid >> 6;          // q-group 0..3 (16 rows each)
    const int kw = (tid >> 5) & 1;    // key-group 0..1
    const int g = lane >> 2, t2 = (lane & 3) * 2;

    const size_t bhoff = (size_t)(b * HH + hd) * SS;
    const __half* Qhg = g_Qh + (bhoff + qt * 64) * DKK;
    const __half* Khg = g_Kh + bhoff * DKK;
    const __half* Vhg = g_Vh + bhoff * DKK;
    const float* mrow = mask + (size_t)b * SS;

    for (int i = tid; i < 64 * 8; i += 256) {
        const int r = i >> 3, c = (i & 7) * 8;
        *(uint4*)&smh[r * 72 + c] = *(const uint4*)(Qhg + r * DKK + c);
    }
    __syncthreads();
    uint32_t qh[4][4];
#pragma unroll
    for (int ks = 0; ks < 4; ks++) {
        const uint32_t off = (uint32_t)((qw * 16 + (lane & 15)) * 144
                                        + (ks * 16 + (lane >> 4) * 8) * 2);
        ldsm_x4(qh[ks], sb + off);
    }
    __syncthreads();

    auto issue = [&](int kt, int stg) {
        const uint32_t base = sb + stg * A_STAGE;
        const size_t goff = (size_t)kt * 64 * DKK;
#pragma unroll
        for (int it = 0; it < 2; it++) {
            const int c = it * 256 + tid;
            const int r = c >> 3, cc = c & 7;
            const uint32_t d = base + (uint32_t)(r * 144 + cc * 16);
            const size_t s = goff + (size_t)r * DKK + cc * 8;
            cpa16(d,        Khg + s);
            cpa16(d + A_VH, Vhg + s);
        }
    };

    float o[8][4];
#pragma unroll
    for (int nd = 0; nd < 8; nd++)
#pragma unroll
        for (int r = 0; r < 4; r++) o[nd][r] = 0.f;
    float lr0 = 0.f, lr1 = 0.f;
    float s[4][4];
    uint32_t pf[2][4];

    auto qkstep = [&](uint32_t st) {
#pragma unroll
        for (int ng = 0; ng < 4; ng++)
#pragma unroll
            for (int r = 0; r < 4; r++) s[ng][r] = 0.f;
#pragma unroll
        for (int ks = 0; ks < 4; ks++) {
            uint32_t bh4[2][4];
#pragma unroll
            for (int pg = 0; pg < 2; pg++) {
                const uint32_t a = st + (uint32_t)(
                    (kw * 32 + pg * 16 + ((lane >> 4) & 1) * 8 + (lane & 7)) * 144
                    + (ks * 16 + ((lane >> 3) & 1) * 8) * 2);
                ldsm_x4(bh4[pg], a);
            }
#pragma unroll
            for (int pg = 0; pg < 2; pg++)
#pragma unroll
                for (int half = 0; half < 2; half++)
                    mma_f16(s[pg * 2 + half], qh[ks], &bh4[pg][half * 2]);
        }
    };

    auto pvstep = [&](uint32_t st) {
#pragma unroll
        for (int ksp = 0; ksp < 2; ksp++) {
#pragma unroll
            for (int pd = 0; pd < 4; pd++) {
                uint32_t bh4[4];
                const uint32_t a = st + A_VH + (uint32_t)(
                    (kw * 32 + ksp * 16 + ((lane >> 3) & 1) * 8 + (lane & 7)) * 144
                    + (pd * 16 + ((lane >> 4) & 1) * 8) * 2);
                ldsm_x4t(bh4, a);
#pragma unroll
                for (int half = 0; half < 2; half++)
                    mma_f16(o[pd * 2 + half], pf[ksp], &bh4[half * 2]);
            }
        }
    };

    auto smstep = [&](const float* mk) {
#pragma unroll
        for (int ng = 0; ng < 4; ng++) {
            const float mk0 = mk[ng * 8 + t2], mk1 = mk[ng * 8 + t2 + 1];
            s[ng][0] = __expf(s[ng][0] * 0.125f + mk0);
            s[ng][1] = __expf(s[ng][1] * 0.125f + mk1);
            s[ng][2] = __expf(s[ng][2] * 0.125f + mk0);
            s[ng][3] = __expf(s[ng][3] * 0.125f + mk1);
            lr0 += s[ng][0] + s[ng][1];
            lr1 += s[ng][2] + s[ng][3];
        }
#pragma unroll
        for (int ksp = 0; ksp < 2; ksp++) {
            pf[ksp][0] = pack2h(s[2 * ksp][0],     s[2 * ksp][1]);
            pf[ksp][1] = pack2h(s[2 * ksp][2],     s[2 * ksp][3]);
            pf[ksp][2] = pack2h(s[2 * ksp + 1][0], s[2 * ksp + 1][1]);
            pf[ksp][3] = pack2h(s[2 * ksp + 1][2], s[2 * ksp + 1][3]);
        }
    };

    issue(0, 0); cpa_commit();
    issue(1, 1); cpa_commit();
    issue(2, 2); cpa_commit();
    if (tid < 64) {
        sMask[tid]       = mrow[tid] * (-1e9f);
        sMask[64 + tid]  = mrow[64 + tid] * (-1e9f);
        sMask[128 + tid] = mrow[128 + tid] * (-1e9f);
    }
    cpa_wait<2>();
    __syncthreads();
    qkstep(sb + 0 * A_STAGE);
    smstep(sMask + 0 * 64 + kw * 32);

    for (int t = 0; t < NTILE - 1; t++) {
        if (t + 3 < NTILE) cpa_wait<1>(); else cpa_wait<0>();
        __syncthreads();
        if (t + 3 < NTILE) {
            const int sn = (t + 3) & 3;
            issue(t + 3, sn);
            if (tid < 64) sMask[sn * 64 + tid] = mrow[(t + 3) * 64 + tid] * (-1e9f);
            cpa_commit();
        }
        qkstep(sb + ((t + 1) & 3) * A_STAGE);
        pvstep(sb + (t & 3) * A_STAGE);
        smstep(sMask + ((t + 1) & 3) * 64 + kw * 32);
    }
    pvstep(sb + ((NTILE - 1) & 3) * A_STAGE);

    lr0 += __shfl_xor_sync(0xffffffffu, lr0, 1);
    lr0 += __shfl_xor_sync(0xffffffffu, lr0, 2);
    lr1 += __shfl_xor_sync(0xffffffffu, lr1, 1);
    lr1 += __shfl_xor_sync(0xffffffffu, lr1, 2);

    __syncthreads();

    float* sO = (float*)dynsm;                      // [64][66]
    float* sL = (float*)(dynsm + 64 * 66 * 4);      // [64]
    if (kw == 1) {
#pragma unroll
        for (int hf = 0; hf < 2; hf++) {
            const int idx = qw * 16 + g + hf * 8;
#pragma unroll
            for (int nd = 0; nd < 8; nd++) {
                sO[idx * 66 + nd * 8 + t2]     = o[nd][hf * 2 + 0];
                sO[idx * 66 + nd * 8 + t2 + 1] = o[nd][hf * 2 + 1];
            }
            if ((lane & 3) == 0) sL[idx] = hf ? lr1 : lr0;
        }
    }
    __syncthreads();
    if (kw == 0) {
#pragma unroll
        for (int hf = 0; hf < 2; hf++) {
            const int idx = qw * 16 + g + hf * 8;
            const float lh = hf ? lr1 : lr0;
            const float inv = 1.f / (lh + sL[idx]);
#pragma unroll
            for (int nd = 0; nd < 8; nd++) {
                const float p0 = (o[nd][hf * 2 + 0] + sO[idx * 66 + nd * 8 + t2]) * inv;
                const float p1 = (o[nd][hf * 2 + 1] + sO[idx * 66 + nd * 8 + t2 + 1]) * inv;
                const size_t off = ((size_t)b * SS + qt * 64 + idx) * DD
                                   + hd * DKK + nd * 8 + t2;
                *(uint32_t*)&g_Ctx[off] = pack2h(p0, p1);
            }
        }
    }
}

// ---------------------------------------------------------------------------
extern "C" void kernel_launch(void* const* d_in, const int* in_sizes, int n_in,
                              void* d_out, int out_size)
{
    (void)in_sizes; (void)n_in; (void)out_size;
    const float* query = (const float*)d_in[0];
    const float* key   = (const float*)d_in[1];
    const float* value = (const float*)d_in[2];
    const float* mask  = (const float*)d_in[3];
    const float* Wq = (const float*)d_in[4];
    const float* bq = (const float*)d_in[5];
    const float* Wk = (const float*)d_in[6];
    const float* bk = (const float*)d_in[7];
    const float* Wv = (const float*)d_in[8];
    const float* bv = (const float*)d_in[9];
    const float* Wo = (const float*)d_in[10];
    const float* bo = (const float*)d_in[11];
    float* out = (float*)d_out;

    cudaFuncSetAttribute(gemm_qkv, cudaFuncAttributeMaxDynamicSharedMemorySize, G_DSMEM);
    cudaFuncSetAttribute(gemm_o,   cudaFuncAttributeMaxDynamicSharedMemorySize, G_DSMEM);
    cudaFuncSetAttribute(attn_mma, cudaFuncAttributeMaxDynamicSharedMemorySize, A_DSMEM);

    SplitArgs sa;
    sa.src[0] = query; sa.src[1] = key; sa.src[2] = value;
    sa.src[3] = Wq; sa.src[4] = Wk; sa.src[5] = Wv; sa.src[6] = Wo;

    split7<<<TOT4 / 512, 256>>>(sa);
    gemm_qkv<<<dim3(DD / 128, M_TOT / 128, 3), 256, G_DSMEM>>>(bq, bk, bv);
    attn_mma<<<dim3(SS / 64, HH, BB), 256, A_DSMEM>>>(mask);
    gemm_o<<<dim3(DD / 128, M_TOT / 128), 256, G_DSMEM>>>(bo, out);
}